// round 1
// baseline (speedup 1.0000x reference)
#include <cuda_runtime.h>
#include <math.h>

#define T_SEQ  2048
#define DIM_C  2048
#define NH     16
#define HD     128
#define QKV_N  6144      // 3 * 2048, row layout [t][e*2048 + h*128 + d]
#define ATTN_SCALE 0.12f

// Scratch (static device allocations are the sanctioned path)
__device__ float g_qkv[(size_t)T_SEQ * QKV_N];   // 50 MB
__device__ float g_y[(size_t)T_SEQ * DIM_C];     // 16 MB

// ---------------------------------------------------------------------------
// GEMM (TN): C[m][n] = sum_k A[m*K+k] * B[n*K+k]
// 128x128 tile, BK=16, 256 threads, 8x8 per thread, double-buffered smem.
// ---------------------------------------------------------------------------
__global__ __launch_bounds__(256)
void gemm_tn_kernel(const float* __restrict__ A,
                    const float* __restrict__ B,
                    float* __restrict__ C,
                    int M, int N, int K)
{
    __shared__ float Ast[2][16][128];
    __shared__ float Bst[2][16][128];

    const int tid = threadIdx.x;
    const int tx  = tid & 15;
    const int ty  = tid >> 4;
    const int rowBase = blockIdx.y * 128;
    const int colBase = blockIdx.x * 128;

    const float* Ag = A + (size_t)rowBase * K;
    const float* Bg = B + (size_t)colBase * K;

    const int lrow = tid >> 2;          // 0..63
    const int lk   = (tid & 3) << 2;    // 0,4,8,12

    float acc[8][8];
#pragma unroll
    for (int i = 0; i < 8; i++)
#pragma unroll
        for (int j = 0; j < 8; j++) acc[i][j] = 0.0f;

    // prologue: load k-chunk 0 into buffer 0
#pragma unroll
    for (int r = 0; r < 2; r++) {
        int row = lrow + r * 64;
        float4 av = *(const float4*)(Ag + (size_t)row * K + lk);
        Ast[0][lk + 0][row] = av.x; Ast[0][lk + 1][row] = av.y;
        Ast[0][lk + 2][row] = av.z; Ast[0][lk + 3][row] = av.w;
        float4 bv = *(const float4*)(Bg + (size_t)row * K + lk);
        Bst[0][lk + 0][row] = bv.x; Bst[0][lk + 1][row] = bv.y;
        Bst[0][lk + 2][row] = bv.z; Bst[0][lk + 3][row] = bv.w;
    }
    __syncthreads();

    const int nk = K >> 4;
    for (int kt = 0; kt < nk; kt++) {
        const int cur = kt & 1;
        const int nxt = cur ^ 1;
        float4 av[2], bv[2];
        const bool pre = (kt + 1 < nk);
        if (pre) {
            int k0 = (kt + 1) << 4;
#pragma unroll
            for (int r = 0; r < 2; r++) {
                int row = lrow + r * 64;
                av[r] = *(const float4*)(Ag + (size_t)row * K + k0 + lk);
                bv[r] = *(const float4*)(Bg + (size_t)row * K + k0 + lk);
            }
        }
#pragma unroll
        for (int kk = 0; kk < 16; kk++) {
            float a[8], b[8];
            *(float4*)(a)     = *(const float4*)(&Ast[cur][kk][ty * 8]);
            *(float4*)(a + 4) = *(const float4*)(&Ast[cur][kk][ty * 8 + 4]);
            *(float4*)(b)     = *(const float4*)(&Bst[cur][kk][tx * 8]);
            *(float4*)(b + 4) = *(const float4*)(&Bst[cur][kk][tx * 8 + 4]);
#pragma unroll
            for (int i = 0; i < 8; i++)
#pragma unroll
                for (int j = 0; j < 8; j++)
                    acc[i][j] += a[i] * b[j];
        }
        if (pre) {
#pragma unroll
            for (int r = 0; r < 2; r++) {
                int row = lrow + r * 64;
                Ast[nxt][lk + 0][row] = av[r].x; Ast[nxt][lk + 1][row] = av[r].y;
                Ast[nxt][lk + 2][row] = av[r].z; Ast[nxt][lk + 3][row] = av[r].w;
                Bst[nxt][lk + 0][row] = bv[r].x; Bst[nxt][lk + 1][row] = bv[r].y;
                Bst[nxt][lk + 2][row] = bv[r].z; Bst[nxt][lk + 3][row] = bv[r].w;
            }
        }
        __syncthreads();
    }

    float* Cp = C + (size_t)rowBase * N + colBase;
#pragma unroll
    for (int i = 0; i < 8; i++) {
        float4 v0 = make_float4(acc[i][0], acc[i][1], acc[i][2], acc[i][3]);
        float4 v1 = make_float4(acc[i][4], acc[i][5], acc[i][6], acc[i][7]);
        float* dst = Cp + (size_t)(ty * 8 + i) * N + tx * 8;
        *(float4*)(dst)     = v0;
        *(float4*)(dst + 4) = v1;
    }
}

// ---------------------------------------------------------------------------
// Per (t, h): RMSNorm q/k/v, RoPE q/k, v = lam0*v + lam1*ve.  In-place on g_qkv.
// 128 threads (one per d).
// ---------------------------------------------------------------------------
__global__ void postproc_kernel(const float* __restrict__ ve,
                                const float* __restrict__ lam)
{
    const int t = blockIdx.x;
    const int h = blockIdx.y;
    const int d = threadIdx.x;

    __shared__ float red[4];
    __shared__ float buf[128];

    float* base = g_qkv + (size_t)t * QKV_N + h * HD;
    const float lam0 = lam[0];
    const float lam1 = lam[1];

#pragma unroll
    for (int e = 0; e < 3; e++) {
        float val = base[e * 2048 + d];
        float sq = val * val;
#pragma unroll
        for (int o = 16; o > 0; o >>= 1)
            sq += __shfl_xor_sync(0xffffffffu, sq, o);
        if ((d & 31) == 0) red[d >> 5] = sq;
        __syncthreads();
        float mean = (red[0] + red[1] + red[2] + red[3]) * (1.0f / 128.0f);
        float nv = val * rsqrtf(mean + 1e-6f);

        if (e < 2) {
            buf[d] = nv;
            __syncthreads();
            int j = d & 63;
            float c, sn;
            if (j < 32) {
                // match jax: (1/1024)^linspace(0,1,32); compute freq in double,
                // then theta = f32(t) * f32(freq) like the reference
                float fr = (float)pow(1.0 / 1024.0, (double)j / 31.0);
                float th = (float)t * fr;
                c = cosf(th); sn = sinf(th);
            } else {
                c = 1.0f; sn = 0.0f;
            }
            float x1 = buf[j];
            float x2 = buf[j + 64];
            float outv = (d < 64) ? (x1 * c + x2 * sn) : (x2 * c - x1 * sn);
            __syncthreads();           // everyone done reading buf/red before overwrite
            base[e * 2048 + d] = outv;
        } else {
            base[e * 2048 + d] = lam0 * nv + lam1 * ve[(size_t)t * DIM_C + h * HD + d];
        }
    }
}

// ---------------------------------------------------------------------------
// Causal flash attention, fp32. One block per (q-tile=128 rows, head).
// KV tiles of 64. 256 threads: S-tile 8x4/thread, O-tile 8x8/thread.
// smem: Qst[128d][132] (transposed), Kst[128d][68] (transposed),
//       Vs[64][128], Ssm[128][65], row stats.
// ---------------------------------------------------------------------------
__global__ __launch_bounds__(256)
void attn_kernel()
{
    extern __shared__ float sm[];
    float* Qst  = sm;                        // 128*132
    float* Kst  = Qst + 128 * 132;           // 128*68
    float* Vs   = Kst + 128 * 68;            // 64*128
    float* Ssm  = Vs + 64 * 128;             // 128*65
    float* mrow = Ssm + 128 * 65;            // 128
    float* lrow = mrow + 128;                // 128
    float* frow = lrow + 128;                // 128

    const int h     = blockIdx.y;
    const int qt    = (int)gridDim.x - 1 - (int)blockIdx.x;  // big tiles first
    const int qbase = qt * 128;
    const int tid   = threadIdx.x;
    const int tx    = tid & 15;
    const int ty    = tid >> 4;

    if (tid < 128) { mrow[tid] = -INFINITY; lrow[tid] = 0.0f; }

    // load Q tile transposed: Qst[d][r]
    const float* qg = g_qkv + (size_t)qbase * QKV_N + h * HD;
    for (int f = tid; f < 128 * 32; f += 256) {
        int d4 = f >> 7, r = f & 127;
        float4 v = *(const float4*)(qg + (size_t)r * QKV_N + (d4 << 2));
        int db = d4 << 2;
        Qst[(db + 0) * 132 + r] = v.x;
        Qst[(db + 1) * 132 + r] = v.y;
        Qst[(db + 2) * 132 + r] = v.z;
        Qst[(db + 3) * 132 + r] = v.w;
    }

    float acc[8][8];
#pragma unroll
    for (int i = 0; i < 8; i++)
#pragma unroll
        for (int j = 0; j < 8; j++) acc[i][j] = 0.0f;

    __syncthreads();

    const int nkv = 2 * qt + 2;
    for (int kb = 0; kb < nkv; kb++) {
        // K tile transposed: Kst[d][c]  (conflict-free smem stores)
        const float* kg = g_qkv + (size_t)(kb * 64) * QKV_N + 2048 + h * HD;
        for (int f = tid; f < 64 * 32; f += 256) {
            int d4 = f >> 6, c = f & 63;
            float4 v = *(const float4*)(kg + (size_t)c * QKV_N + (d4 << 2));
            int db = d4 << 2;
            Kst[(db + 0) * 68 + c] = v.x;
            Kst[(db + 1) * 68 + c] = v.y;
            Kst[(db + 2) * 68 + c] = v.z;
            Kst[(db + 3) * 68 + c] = v.w;
        }
        // V tile row-major (coalesced)
        const float* vg = g_qkv + (size_t)(kb * 64) * QKV_N + 4096 + h * HD;
        for (int f = tid; f < 64 * 32; f += 256) {
            int c = f >> 5, d4 = f & 31;
            *(float4*)(Vs + c * 128 + (d4 << 2)) =
                *(const float4*)(vg + (size_t)c * QKV_N + (d4 << 2));
        }
        __syncthreads();

        // S = Q K^T  (8 rows x 4 cols per thread)
        float s[8][4];
#pragma unroll
        for (int i = 0; i < 8; i++)
#pragma unroll
            for (int j = 0; j < 4; j++) s[i][j] = 0.0f;

#pragma unroll 4
        for (int kk = 0; kk < 128; kk++) {
            float a[8], b[4];
            *(float4*)(a)     = *(const float4*)(Qst + kk * 132 + ty * 8);
            *(float4*)(a + 4) = *(const float4*)(Qst + kk * 132 + ty * 8 + 4);
            *(float4*)(b)     = *(const float4*)(Kst + kk * 68 + tx * 4);
#pragma unroll
            for (int i = 0; i < 8; i++)
#pragma unroll
                for (int j = 0; j < 4; j++)
                    s[i][j] += a[i] * b[j];
        }

        // scale + causal mask -> smem
#pragma unroll
        for (int i = 0; i < 8; i++) {
            int gr = qbase + ty * 8 + i;
#pragma unroll
            for (int j = 0; j < 4; j++) {
                int gc = kb * 64 + tx * 4 + j;
                float v = s[i][j] * ATTN_SCALE;
                Ssm[(ty * 8 + i) * 65 + tx * 4 + j] = (gc <= gr) ? v : -INFINITY;
            }
        }
        __syncthreads();

        // online softmax row pass (one thread per row)
        if (tid < 128) {
            float* row = Ssm + tid * 65;
            float rmax = -INFINITY;
            for (int c = 0; c < 64; c++) rmax = fmaxf(rmax, row[c]);
            float m_old = mrow[tid];
            float m_new = fmaxf(m_old, rmax);
            float fr = __expf(m_old - m_new);
            float sum = 0.0f;
            for (int c = 0; c < 64; c++) {
                float p = __expf(row[c] - m_new);
                row[c] = p;
                sum += p;
            }
            lrow[tid] = lrow[tid] * fr + sum;
            mrow[tid] = m_new;
            frow[tid] = fr;
        }
        __syncthreads();

        // rescale accumulators + P @ V
        float fv[8];
#pragma unroll
        for (int i = 0; i < 8; i++) fv[i] = frow[ty * 8 + i];
#pragma unroll
        for (int i = 0; i < 8; i++)
#pragma unroll
            for (int j = 0; j < 8; j++) acc[i][j] *= fv[i];

#pragma unroll 2
        for (int c = 0; c < 64; c++) {
            float p[8];
#pragma unroll
            for (int i = 0; i < 8; i++) p[i] = Ssm[(ty * 8 + i) * 65 + c];
            float v[8];
            *(float4*)(v)     = *(const float4*)(Vs + c * 128 + tx * 8);
            *(float4*)(v + 4) = *(const float4*)(Vs + c * 128 + tx * 8 + 4);
#pragma unroll
            for (int i = 0; i < 8; i++)
#pragma unroll
                for (int j = 0; j < 8; j++)
                    acc[i][j] += p[i] * v[j];
        }
        __syncthreads();
    }

    // epilogue: normalize and write y[t][h*128+d]
#pragma unroll
    for (int i = 0; i < 8; i++) {
        float inv = 1.0f / lrow[ty * 8 + i];
        float o[8];
#pragma unroll
        for (int j = 0; j < 8; j++) o[j] = acc[i][j] * inv;
        float* dst = g_y + (size_t)(qbase + ty * 8 + i) * DIM_C + h * HD + tx * 8;
        *(float4*)(dst)     = *(float4*)(o);
        *(float4*)(dst + 4) = *(float4*)(o + 4);
    }
}

// ---------------------------------------------------------------------------
extern "C" void kernel_launch(void* const* d_in, const int* in_sizes, int n_in,
                              void* d_out, int out_size)
{
    const float* x   = (const float*)d_in[0];   // [1,2048,2048]
    const float* w   = (const float*)d_in[1];   // [4,2048,2048]
    const float* ve  = (const float*)d_in[2];   // [1,2048,2048]
    const float* lam = (const float*)d_in[3];   // [2]
    float* out = (float*)d_out;                 // [1,2048,2048] f32

    float* qkv_ptr = nullptr;
    float* y_ptr   = nullptr;
    cudaGetSymbolAddress((void**)&qkv_ptr, g_qkv);
    cudaGetSymbolAddress((void**)&y_ptr,   g_y);

    // 1) QKV projection: [2048,2048] x [6144,2048]^T -> g_qkv
    gemm_tn_kernel<<<dim3(48, 16), 256>>>(x, w, qkv_ptr, 2048, 6144, 2048);

    // 2) RMSNorm + RoPE + v blend (in-place on g_qkv)
    postproc_kernel<<<dim3(2048, 16), 128>>>(ve, lam);

    // 3) causal attention -> g_y
    size_t smem = (size_t)(128 * 132 + 128 * 68 + 64 * 128 + 128 * 65 + 3 * 128)
                  * sizeof(float);   // 169,984 B
    cudaFuncSetAttribute(attn_kernel,
                         cudaFuncAttributeMaxDynamicSharedMemorySize, (int)smem);
    attn_kernel<<<dim3(16, 16), 256, smem>>>();

    // 4) output projection: [2048,2048] x [2048,2048]^T -> out
    gemm_tn_kernel<<<dim3(16, 16), 256>>>(y_ptr, w + (size_t)3 * 2048 * 2048, out,
                                          2048, 2048, 2048);
}

// round 2
// speedup vs baseline: 1.5032x; 1.5032x over previous
#include <cuda_runtime.h>
#include <math.h>

#define T_SEQ  2048
#define DIM_C  2048
#define NH     16
#define HD     128
#define QKV_N  6144      // 3 * 2048, row layout [t][e*2048 + h*128 + d]
#define ATTN_SCALE 0.12f

// Scratch
__device__ float g_qkv[(size_t)T_SEQ * QKV_N];   // 50 MB
__device__ float g_y[(size_t)T_SEQ * DIM_C];     // 16 MB

// ---------------------------------------------------------------------------
// tf32 helpers
// ---------------------------------------------------------------------------
__device__ __forceinline__ float tf32r(float x) {
    unsigned u;
    asm("cvt.rna.tf32.f32 %0, %1;" : "=r"(u) : "f"(x));
    return __uint_as_float(u);
}

__device__ __forceinline__ void mma_tf32(float* d, const float* a, const float* b) {
    asm volatile(
        "mma.sync.aligned.m16n8k8.row.col.f32.tf32.tf32.f32 "
        "{%0,%1,%2,%3}, {%4,%5,%6,%7}, {%8,%9}, {%0,%1,%2,%3};\n"
        : "+f"(d[0]), "+f"(d[1]), "+f"(d[2]), "+f"(d[3])
        : "r"(__float_as_uint(a[0])), "r"(__float_as_uint(a[1])),
          "r"(__float_as_uint(a[2])), "r"(__float_as_uint(a[3])),
          "r"(__float_as_uint(b[0])), "r"(__float_as_uint(b[1])));
}

// ---------------------------------------------------------------------------
// GEMM (TN) on tensor cores: C[m][n] = sum_k A[m*K+k] * B[n*K+k]
// 128x128 block tile, BK=32, 256 threads = 8 warps (2x4), warp tile 64x32.
// mma.sync m16n8k8 tf32, inputs RNA-rounded to tf32 at smem store.
// smem layout [row][36] (pad 36: conflict-free frag loads: (4g+tig) mod 32).
// ---------------------------------------------------------------------------
#define GSPAD 36
#define GBUF  (128 * GSPAD)

__global__ __launch_bounds__(256, 2)
void gemm_tf32_kernel(const float* __restrict__ A,
                      const float* __restrict__ B,
                      float* __restrict__ C,
                      int M, int N, int K)
{
    extern __shared__ float smg[];
    float* As = smg;                 // [2][128][36]
    float* Bs = smg + 2 * GBUF;      // [2][128][36]

    const int tid  = threadIdx.x;
    const int lane = tid & 31;
    const int wid  = tid >> 5;
    const int g    = lane >> 2;      // groupID 0..7
    const int tig  = lane & 3;       // thread-in-group

    const int wm = (wid & 1) * 64;   // warp row offset
    const int wn = (wid >> 1) * 32;  // warp col offset

    const int rowBase = blockIdx.y * 128;
    const int colBase = blockIdx.x * 128;

    const float* Ag = A + (size_t)rowBase * K;
    const float* Bg = B + (size_t)colBase * K;

    // global->smem mapping: each thread moves 4 float4 per tile per operand
    const int c4 = (tid & 7) << 2;   // k offset (floats)
    const int r0 = tid >> 3;         // row 0..31 (+32*i)

    float acc[4][4][4];
#pragma unroll
    for (int mi = 0; mi < 4; mi++)
#pragma unroll
        for (int ni = 0; ni < 4; ni++)
#pragma unroll
            for (int c = 0; c < 4; c++) acc[mi][ni][c] = 0.0f;

    // prologue: k-chunk 0 -> buffer 0 (with tf32 rounding)
#pragma unroll
    for (int i = 0; i < 4; i++) {
        int r = r0 + 32 * i;
        float4 av = *(const float4*)(Ag + (size_t)r * K + c4);
        float4 bv = *(const float4*)(Bg + (size_t)r * K + c4);
        *(float4*)&As[r * GSPAD + c4] =
            make_float4(tf32r(av.x), tf32r(av.y), tf32r(av.z), tf32r(av.w));
        *(float4*)&Bs[r * GSPAD + c4] =
            make_float4(tf32r(bv.x), tf32r(bv.y), tf32r(bv.z), tf32r(bv.w));
    }
    __syncthreads();

    const int nk = K >> 5;
    for (int kt = 0; kt < nk; kt++) {
        const int cur = kt & 1;
        float4 ar[4], br[4];
        const bool pre = (kt + 1 < nk);
        if (pre) {
            int k0 = (kt + 1) << 5;
#pragma unroll
            for (int i = 0; i < 4; i++) {
                int r = r0 + 32 * i;
                ar[i] = *(const float4*)(Ag + (size_t)r * K + k0 + c4);
                br[i] = *(const float4*)(Bg + (size_t)r * K + k0 + c4);
            }
        }

        const float* Ac = As + cur * GBUF;
        const float* Bc = Bs + cur * GBUF;

#pragma unroll
        for (int ks = 0; ks < 4; ks++) {
            const int k0 = ks * 8;
            float a[4][4];
#pragma unroll
            for (int mi = 0; mi < 4; mi++) {
                const float* p  = Ac + (wm + mi * 16 + g) * GSPAD + k0 + tig;
                const float* p8 = p + 8 * GSPAD;
                a[mi][0] = p[0];
                a[mi][1] = p8[0];
                a[mi][2] = p[4];
                a[mi][3] = p8[4];
            }
            float b[4][2];
#pragma unroll
            for (int ni = 0; ni < 4; ni++) {
                const float* p = Bc + (wn + ni * 8 + g) * GSPAD + k0 + tig;
                b[ni][0] = p[0];
                b[ni][1] = p[4];
            }
#pragma unroll
            for (int mi = 0; mi < 4; mi++)
#pragma unroll
                for (int ni = 0; ni < 4; ni++)
                    mma_tf32(acc[mi][ni], a[mi], b[ni]);
        }

        if (pre) {
            float* An = As + (cur ^ 1) * GBUF;
            float* Bn = Bs + (cur ^ 1) * GBUF;
#pragma unroll
            for (int i = 0; i < 4; i++) {
                int r = r0 + 32 * i;
                *(float4*)&An[r * GSPAD + c4] =
                    make_float4(tf32r(ar[i].x), tf32r(ar[i].y), tf32r(ar[i].z), tf32r(ar[i].w));
                *(float4*)&Bn[r * GSPAD + c4] =
                    make_float4(tf32r(br[i].x), tf32r(br[i].y), tf32r(br[i].z), tf32r(br[i].w));
            }
        }
        __syncthreads();
    }

    // epilogue
    float* Cp = C + (size_t)rowBase * N + colBase;
#pragma unroll
    for (int mi = 0; mi < 4; mi++) {
        int m = wm + mi * 16 + g;
#pragma unroll
        for (int ni = 0; ni < 4; ni++) {
            int n = wn + ni * 8 + tig * 2;
            *(float2*)&Cp[(size_t)m * N + n] =
                make_float2(acc[mi][ni][0], acc[mi][ni][1]);
            *(float2*)&Cp[(size_t)(m + 8) * N + n] =
                make_float2(acc[mi][ni][2], acc[mi][ni][3]);
        }
    }
}

// ---------------------------------------------------------------------------
// Per (t, h): RMSNorm q/k/v, RoPE q/k, v = lam0*v + lam1*ve.  In-place.
// ---------------------------------------------------------------------------
__global__ void postproc_kernel(const float* __restrict__ ve,
                                const float* __restrict__ lam)
{
    const int t = blockIdx.x;
    const int h = blockIdx.y;
    const int d = threadIdx.x;

    __shared__ float red[4];
    __shared__ float buf[128];

    float* base = g_qkv + (size_t)t * QKV_N + h * HD;
    const float lam0 = lam[0];
    const float lam1 = lam[1];

#pragma unroll
    for (int e = 0; e < 3; e++) {
        float val = base[e * 2048 + d];
        float sq = val * val;
#pragma unroll
        for (int o = 16; o > 0; o >>= 1)
            sq += __shfl_xor_sync(0xffffffffu, sq, o);
        if ((d & 31) == 0) red[d >> 5] = sq;
        __syncthreads();
        float mean = (red[0] + red[1] + red[2] + red[3]) * (1.0f / 128.0f);
        float nv = val * rsqrtf(mean + 1e-6f);

        if (e < 2) {
            buf[d] = nv;
            __syncthreads();
            int j = d & 63;
            float c, sn;
            if (j < 32) {
                float fr = (float)pow(1.0 / 1024.0, (double)j / 31.0);
                float th = (float)t * fr;
                c = cosf(th); sn = sinf(th);
            } else {
                c = 1.0f; sn = 0.0f;
            }
            float x1 = buf[j];
            float x2 = buf[j + 64];
            float outv = (d < 64) ? (x1 * c + x2 * sn) : (x2 * c - x1 * sn);
            __syncthreads();
            base[e * 2048 + d] = outv;
        } else {
            base[e * 2048 + d] = lam0 * nv + lam1 * ve[(size_t)t * DIM_C + h * HD + d];
        }
    }
}

// ---------------------------------------------------------------------------
// Causal flash attention, fp32 (softmax pass now 2 threads/row).
// ---------------------------------------------------------------------------
__global__ __launch_bounds__(256)
void attn_kernel()
{
    extern __shared__ float sm[];
    float* Qst  = sm;                        // 128*132
    float* Kst  = Qst + 128 * 132;           // 128*68
    float* Vs   = Kst + 128 * 68;            // 64*128
    float* Ssm  = Vs + 64 * 128;             // 128*65
    float* mrow = Ssm + 128 * 65;            // 128
    float* lrow = mrow + 128;                // 128
    float* frow = lrow + 128;                // 128

    const int h     = blockIdx.y;
    const int qt    = (int)gridDim.x - 1 - (int)blockIdx.x;
    const int qbase = qt * 128;
    const int tid   = threadIdx.x;
    const int tx    = tid & 15;
    const int ty    = tid >> 4;

    if (tid < 128) { mrow[tid] = -INFINITY; lrow[tid] = 0.0f; }

    const float* qg = g_qkv + (size_t)qbase * QKV_N + h * HD;
    for (int f = tid; f < 128 * 32; f += 256) {
        int d4 = f >> 7, r = f & 127;
        float4 v = *(const float4*)(qg + (size_t)r * QKV_N + (d4 << 2));
        int db = d4 << 2;
        Qst[(db + 0) * 132 + r] = v.x;
        Qst[(db + 1) * 132 + r] = v.y;
        Qst[(db + 2) * 132 + r] = v.z;
        Qst[(db + 3) * 132 + r] = v.w;
    }

    float acc[8][8];
#pragma unroll
    for (int i = 0; i < 8; i++)
#pragma unroll
        for (int j = 0; j < 8; j++) acc[i][j] = 0.0f;

    __syncthreads();

    const int nkv = 2 * qt + 2;
    for (int kb = 0; kb < nkv; kb++) {
        const float* kg = g_qkv + (size_t)(kb * 64) * QKV_N + 2048 + h * HD;
        for (int f = tid; f < 64 * 32; f += 256) {
            int d4 = f >> 6, c = f & 63;
            float4 v = *(const float4*)(kg + (size_t)c * QKV_N + (d4 << 2));
            int db = d4 << 2;
            Kst[(db + 0) * 68 + c] = v.x;
            Kst[(db + 1) * 68 + c] = v.y;
            Kst[(db + 2) * 68 + c] = v.z;
            Kst[(db + 3) * 68 + c] = v.w;
        }
        const float* vg = g_qkv + (size_t)(kb * 64) * QKV_N + 4096 + h * HD;
        for (int f = tid; f < 64 * 32; f += 256) {
            int c = f >> 5, d4 = f & 31;
            *(float4*)(Vs + c * 128 + (d4 << 2)) =
                *(const float4*)(vg + (size_t)c * QKV_N + (d4 << 2));
        }
        __syncthreads();

        // S = Q K^T
        float s[8][4];
#pragma unroll
        for (int i = 0; i < 8; i++)
#pragma unroll
            for (int j = 0; j < 4; j++) s[i][j] = 0.0f;

#pragma unroll 4
        for (int kk = 0; kk < 128; kk++) {
            float a[8], b[4];
            *(float4*)(a)     = *(const float4*)(Qst + kk * 132 + ty * 8);
            *(float4*)(a + 4) = *(const float4*)(Qst + kk * 132 + ty * 8 + 4);
            *(float4*)(b)     = *(const float4*)(Kst + kk * 68 + tx * 4);
#pragma unroll
            for (int i = 0; i < 8; i++)
#pragma unroll
                for (int j = 0; j < 4; j++)
                    s[i][j] += a[i] * b[j];
        }

#pragma unroll
        for (int i = 0; i < 8; i++) {
            int gr = qbase + ty * 8 + i;
#pragma unroll
            for (int j = 0; j < 4; j++) {
                int gc = kb * 64 + tx * 4 + j;
                float v = s[i][j] * ATTN_SCALE;
                Ssm[(ty * 8 + i) * 65 + tx * 4 + j] = (gc <= gr) ? v : -INFINITY;
            }
        }
        __syncthreads();

        // online softmax row pass: 2 threads per row
        {
            const int r  = tid >> 1;
            const int hf = tid & 1;
            float* row = Ssm + r * 65 + hf * 32;
            float rmax = -INFINITY;
#pragma unroll
            for (int c = 0; c < 32; c++) rmax = fmaxf(rmax, row[c]);
            rmax = fmaxf(rmax, __shfl_xor_sync(0xffffffffu, rmax, 1));
            float m_old = mrow[r];
            float m_new = fmaxf(m_old, rmax);
            float fr = __expf(m_old - m_new);
            float sum = 0.0f;
#pragma unroll
            for (int c = 0; c < 32; c++) {
                float p = __expf(row[c] - m_new);
                row[c] = p;
                sum += p;
            }
            sum += __shfl_xor_sync(0xffffffffu, sum, 1);
            if (hf == 0) {
                lrow[r] = lrow[r] * fr + sum;
                mrow[r] = m_new;
                frow[r] = fr;
            }
        }
        __syncthreads();

        float fv[8];
#pragma unroll
        for (int i = 0; i < 8; i++) fv[i] = frow[ty * 8 + i];
#pragma unroll
        for (int i = 0; i < 8; i++)
#pragma unroll
            for (int j = 0; j < 8; j++) acc[i][j] *= fv[i];

#pragma unroll 2
        for (int c = 0; c < 64; c++) {
            float p[8];
#pragma unroll
            for (int i = 0; i < 8; i++) p[i] = Ssm[(ty * 8 + i) * 65 + c];
            float v[8];
            *(float4*)(v)     = *(const float4*)(Vs + c * 128 + tx * 8);
            *(float4*)(v + 4) = *(const float4*)(Vs + c * 128 + tx * 8 + 4);
#pragma unroll
            for (int i = 0; i < 8; i++)
#pragma unroll
                for (int j = 0; j < 8; j++)
                    acc[i][j] += p[i] * v[j];
        }
        __syncthreads();
    }

#pragma unroll
    for (int i = 0; i < 8; i++) {
        float inv = 1.0f / lrow[ty * 8 + i];
        float o[8];
#pragma unroll
        for (int j = 0; j < 8; j++) o[j] = acc[i][j] * inv;
        float* dst = g_y + (size_t)(qbase + ty * 8 + i) * DIM_C + h * HD + tx * 8;
        *(float4*)(dst)     = *(float4*)(o);
        *(float4*)(dst + 4) = *(float4*)(o + 4);
    }
}

// ---------------------------------------------------------------------------
extern "C" void kernel_launch(void* const* d_in, const int* in_sizes, int n_in,
                              void* d_out, int out_size)
{
    const float* x   = (const float*)d_in[0];   // [1,2048,2048]
    const float* w   = (const float*)d_in[1];   // [4,2048,2048]
    const float* ve  = (const float*)d_in[2];   // [1,2048,2048]
    const float* lam = (const float*)d_in[3];   // [2]
    float* out = (float*)d_out;                 // [1,2048,2048] f32

    float* qkv_ptr = nullptr;
    float* y_ptr   = nullptr;
    cudaGetSymbolAddress((void**)&qkv_ptr, g_qkv);
    cudaGetSymbolAddress((void**)&y_ptr,   g_y);

    const int gemm_smem = 4 * GBUF * (int)sizeof(float);   // 73728 B
    cudaFuncSetAttribute(gemm_tf32_kernel,
                         cudaFuncAttributeMaxDynamicSharedMemorySize, gemm_smem);

    // 1) QKV projection: [2048,2048] x [6144,2048]^T -> g_qkv
    gemm_tf32_kernel<<<dim3(48, 16), 256, gemm_smem>>>(x, w, qkv_ptr, 2048, 6144, 2048);

    // 2) RMSNorm + RoPE + v blend (in-place on g_qkv)
    postproc_kernel<<<dim3(2048, 16), 128>>>(ve, lam);

    // 3) causal attention -> g_y
    size_t smem = (size_t)(128 * 132 + 128 * 68 + 64 * 128 + 128 * 65 + 3 * 128)
                  * sizeof(float);   // 169,984 B
    cudaFuncSetAttribute(attn_kernel,
                         cudaFuncAttributeMaxDynamicSharedMemorySize, (int)smem);
    attn_kernel<<<dim3(16, 16), 256, smem>>>();

    // 4) output projection: [2048,2048] x [2048,2048]^T -> out
    gemm_tf32_kernel<<<dim3(16, 16), 256, gemm_smem>>>(y_ptr, w + (size_t)3 * 2048 * 2048, out,
                                                       2048, 2048, 2048);
}

// round 3
// speedup vs baseline: 1.9731x; 1.3126x over previous
#include <cuda_runtime.h>
#include <math.h>

#define T_SEQ  2048
#define DIM_C  2048
#define NH     16
#define HD     128
#define QKV_N  6144      // 3 * 2048, row layout [t][e*2048 + h*128 + d]
#define ATTN_SCALE 0.12f

// Scratch
__device__ float g_qkv[(size_t)T_SEQ * QKV_N];   // 50 MB
__device__ float g_y[(size_t)T_SEQ * DIM_C];     // 16 MB

// ---------------------------------------------------------------------------
// tf32 helpers
// ---------------------------------------------------------------------------
__device__ __forceinline__ float tf32r(float x) {
    unsigned u;
    asm("cvt.rna.tf32.f32 %0, %1;" : "=r"(u) : "f"(x));
    return __uint_as_float(u);
}

__device__ __forceinline__ void mma_tf32(float* d, const float* a, const float* b) {
    asm volatile(
        "mma.sync.aligned.m16n8k8.row.col.f32.tf32.tf32.f32 "
        "{%0,%1,%2,%3}, {%4,%5,%6,%7}, {%8,%9}, {%0,%1,%2,%3};\n"
        : "+f"(d[0]), "+f"(d[1]), "+f"(d[2]), "+f"(d[3])
        : "r"(__float_as_uint(a[0])), "r"(__float_as_uint(a[1])),
          "r"(__float_as_uint(a[2])), "r"(__float_as_uint(a[3])),
          "r"(__float_as_uint(b[0])), "r"(__float_as_uint(b[1])));
}

// ---------------------------------------------------------------------------
// GEMM (TN) on tensor cores (unchanged from R1)
// ---------------------------------------------------------------------------
#define GSPAD 36
#define GBUF  (128 * GSPAD)

__global__ __launch_bounds__(256, 2)
void gemm_tf32_kernel(const float* __restrict__ A,
                      const float* __restrict__ B,
                      float* __restrict__ C,
                      int M, int N, int K)
{
    extern __shared__ float smg[];
    float* As = smg;                 // [2][128][36]
    float* Bs = smg + 2 * GBUF;      // [2][128][36]

    const int tid  = threadIdx.x;
    const int lane = tid & 31;
    const int wid  = tid >> 5;
    const int g    = lane >> 2;
    const int tig  = lane & 3;

    const int wm = (wid & 1) * 64;
    const int wn = (wid >> 1) * 32;

    const int rowBase = blockIdx.y * 128;
    const int colBase = blockIdx.x * 128;

    const float* Ag = A + (size_t)rowBase * K;
    const float* Bg = B + (size_t)colBase * K;

    const int c4 = (tid & 7) << 2;
    const int r0 = tid >> 3;

    float acc[4][4][4];
#pragma unroll
    for (int mi = 0; mi < 4; mi++)
#pragma unroll
        for (int ni = 0; ni < 4; ni++)
#pragma unroll
            for (int c = 0; c < 4; c++) acc[mi][ni][c] = 0.0f;

#pragma unroll
    for (int i = 0; i < 4; i++) {
        int r = r0 + 32 * i;
        float4 av = *(const float4*)(Ag + (size_t)r * K + c4);
        float4 bv = *(const float4*)(Bg + (size_t)r * K + c4);
        *(float4*)&As[r * GSPAD + c4] =
            make_float4(tf32r(av.x), tf32r(av.y), tf32r(av.z), tf32r(av.w));
        *(float4*)&Bs[r * GSPAD + c4] =
            make_float4(tf32r(bv.x), tf32r(bv.y), tf32r(bv.z), tf32r(bv.w));
    }
    __syncthreads();

    const int nk = K >> 5;
    for (int kt = 0; kt < nk; kt++) {
        const int cur = kt & 1;
        float4 ar[4], br[4];
        const bool pre = (kt + 1 < nk);
        if (pre) {
            int k0 = (kt + 1) << 5;
#pragma unroll
            for (int i = 0; i < 4; i++) {
                int r = r0 + 32 * i;
                ar[i] = *(const float4*)(Ag + (size_t)r * K + k0 + c4);
                br[i] = *(const float4*)(Bg + (size_t)r * K + k0 + c4);
            }
        }

        const float* Ac = As + cur * GBUF;
        const float* Bc = Bs + cur * GBUF;

#pragma unroll
        for (int ks = 0; ks < 4; ks++) {
            const int k0 = ks * 8;
            float a[4][4];
#pragma unroll
            for (int mi = 0; mi < 4; mi++) {
                const float* p  = Ac + (wm + mi * 16 + g) * GSPAD + k0 + tig;
                const float* p8 = p + 8 * GSPAD;
                a[mi][0] = p[0];
                a[mi][1] = p8[0];
                a[mi][2] = p[4];
                a[mi][3] = p8[4];
            }
            float b[4][2];
#pragma unroll
            for (int ni = 0; ni < 4; ni++) {
                const float* p = Bc + (wn + ni * 8 + g) * GSPAD + k0 + tig;
                b[ni][0] = p[0];
                b[ni][1] = p[4];
            }
#pragma unroll
            for (int mi = 0; mi < 4; mi++)
#pragma unroll
                for (int ni = 0; ni < 4; ni++)
                    mma_tf32(acc[mi][ni], a[mi], b[ni]);
        }

        if (pre) {
            float* An = As + (cur ^ 1) * GBUF;
            float* Bn = Bs + (cur ^ 1) * GBUF;
#pragma unroll
            for (int i = 0; i < 4; i++) {
                int r = r0 + 32 * i;
                *(float4*)&An[r * GSPAD + c4] =
                    make_float4(tf32r(ar[i].x), tf32r(ar[i].y), tf32r(ar[i].z), tf32r(ar[i].w));
                *(float4*)&Bn[r * GSPAD + c4] =
                    make_float4(tf32r(br[i].x), tf32r(br[i].y), tf32r(br[i].z), tf32r(br[i].w));
            }
        }
        __syncthreads();
    }

    float* Cp = C + (size_t)rowBase * N + colBase;
#pragma unroll
    for (int mi = 0; mi < 4; mi++) {
        int m = wm + mi * 16 + g;
#pragma unroll
        for (int ni = 0; ni < 4; ni++) {
            int n = wn + ni * 8 + tig * 2;
            *(float2*)&Cp[(size_t)m * N + n] =
                make_float2(acc[mi][ni][0], acc[mi][ni][1]);
            *(float2*)&Cp[(size_t)(m + 8) * N + n] =
                make_float2(acc[mi][ni][2], acc[mi][ni][3]);
        }
    }
}

// ---------------------------------------------------------------------------
// Per (t, h): RMSNorm q/k/v, RoPE q/k, v = lam0*v + lam1*ve.  In-place.
// ---------------------------------------------------------------------------
__global__ void postproc_kernel(const float* __restrict__ ve,
                                const float* __restrict__ lam)
{
    const int t = blockIdx.x;
    const int h = blockIdx.y;
    const int d = threadIdx.x;

    __shared__ float red[4];
    __shared__ float buf[128];

    float* base = g_qkv + (size_t)t * QKV_N + h * HD;
    const float lam0 = lam[0];
    const float lam1 = lam[1];

#pragma unroll
    for (int e = 0; e < 3; e++) {
        float val = base[e * 2048 + d];
        float sq = val * val;
#pragma unroll
        for (int o = 16; o > 0; o >>= 1)
            sq += __shfl_xor_sync(0xffffffffu, sq, o);
        if ((d & 31) == 0) red[d >> 5] = sq;
        __syncthreads();
        float mean = (red[0] + red[1] + red[2] + red[3]) * (1.0f / 128.0f);
        float nv = val * rsqrtf(mean + 1e-6f);

        if (e < 2) {
            buf[d] = nv;
            __syncthreads();
            int j = d & 63;
            float c, sn;
            if (j < 32) {
                float fr = (float)pow(1.0 / 1024.0, (double)j / 31.0);
                float th = (float)t * fr;
                c = cosf(th); sn = sinf(th);
            } else {
                c = 1.0f; sn = 0.0f;
            }
            float x1 = buf[j];
            float x2 = buf[j + 64];
            float outv = (d < 64) ? (x1 * c + x2 * sn) : (x2 * c - x1 * sn);
            __syncthreads();
            base[e * 2048 + d] = outv;
        } else {
            base[e * 2048 + d] = lam0 * nv + lam1 * ve[(size_t)t * DIM_C + h * HD + d];
        }
    }
}

// ---------------------------------------------------------------------------
// Causal flash attention on tensor cores (tf32 mma, fp32 softmax).
// Block: 128 q-rows x one head. 256 threads = 8 warps; warp w owns rows
// [16w,16w+16). KV tiles of 64. Row stats live in registers (quad shfl).
// smem: Qs[128][132], Ks[64][132] (B col-major), Vst[128][68] (V^T),
//       Ps[128][68] (P round-trip).  Frag loads hit banks (4g+tig): clean.
// ---------------------------------------------------------------------------
#define QS_OFF   0
#define KS_OFF   (128 * 132)
#define VST_OFF  (KS_OFF + 64 * 132)
#define PS_OFF   (VST_OFF + 128 * 68)
#define ATTN_SMEM ((PS_OFF + 128 * 68) * 4)

__global__ __launch_bounds__(256)
void attn_kernel()
{
    extern __shared__ float sm[];
    float* Qs  = sm + QS_OFF;
    float* Ks  = sm + KS_OFF;
    float* Vst = sm + VST_OFF;
    float* Ps  = sm + PS_OFF;

    const int h     = blockIdx.y;
    const int qt    = (int)gridDim.x - 1 - (int)blockIdx.x;
    const int qbase = qt * 128;
    const int tid   = threadIdx.x;
    const int lane  = tid & 31;
    const int wid   = tid >> 5;
    const int g     = lane >> 2;
    const int tig   = lane & 3;
    const int rw    = wid * 16;

    // load Q tile (tf32-rounded), coalesced
    const float* qg = g_qkv + (size_t)qbase * QKV_N + h * HD;
    for (int f = tid; f < 128 * 32; f += 256) {
        int r = f >> 5, d4 = (f & 31) << 2;
        float4 v = *(const float4*)(qg + (size_t)r * QKV_N + d4);
        *(float4*)&Qs[r * 132 + d4] =
            make_float4(tf32r(v.x), tf32r(v.y), tf32r(v.z), tf32r(v.w));
    }

    float oacc[16][4];
#pragma unroll
    for (int nd = 0; nd < 16; nd++)
#pragma unroll
        for (int c = 0; c < 4; c++) oacc[nd][c] = 0.0f;

    float m0 = -INFINITY, m1 = -INFINITY, l0 = 0.0f, l1 = 0.0f;

    __syncthreads();

    const int nkv = 2 * qt + 2;
    for (int kb = 0; kb < nkv; kb++) {
        // K tile: Ks[c][k], coalesced load, direct store
        const float* kg = g_qkv + (size_t)(kb * 64) * QKV_N + 2048 + h * HD;
        for (int f = tid; f < 64 * 32; f += 256) {
            int c = f >> 5, d4 = (f & 31) << 2;
            float4 v = *(const float4*)(kg + (size_t)c * QKV_N + d4);
            *(float4*)&Ks[c * 132 + d4] =
                make_float4(tf32r(v.x), tf32r(v.y), tf32r(v.z), tf32r(v.w));
        }
        // V tile transposed: Vst[d][c] (conflict-free column-scatter stores)
        const float* vg = g_qkv + (size_t)(kb * 64) * QKV_N + 4096 + h * HD;
        for (int f = tid; f < 64 * 32; f += 256) {
            int d4 = (f >> 6) << 2, c = f & 63;
            float4 v = *(const float4*)(vg + (size_t)c * QKV_N + d4);
            Vst[(d4 + 0) * 68 + c] = tf32r(v.x);
            Vst[(d4 + 1) * 68 + c] = tf32r(v.y);
            Vst[(d4 + 2) * 68 + c] = tf32r(v.z);
            Vst[(d4 + 3) * 68 + c] = tf32r(v.w);
        }
        __syncthreads();

        // ---- S = Q K^T (warp: 16 rows x 64 cols) ----
        float sacc[8][4];
#pragma unroll
        for (int ni = 0; ni < 8; ni++)
#pragma unroll
            for (int c = 0; c < 4; c++) sacc[ni][c] = 0.0f;

#pragma unroll
        for (int k0 = 0; k0 < 128; k0 += 8) {
            float a[4];
            const float* ap = Qs + (rw + g) * 132 + k0 + tig;
            a[0] = ap[0];
            a[1] = ap[8 * 132];
            a[2] = ap[4];
            a[3] = ap[8 * 132 + 4];
#pragma unroll
            for (int ni = 0; ni < 8; ni++) {
                float b[2];
                const float* bp = Ks + (ni * 8 + g) * 132 + k0 + tig;
                b[0] = bp[0];
                b[1] = bp[4];
                mma_tf32(sacc[ni], a, b);
            }
        }

        // ---- scale + mask + online softmax (register row stats) ----
        const int row0 = qbase + rw + g;
        const int row1 = row0 + 8;
        const int cbase = kb * 64;
        const bool needmask = (kb >= 2 * qt);

        float rmax0 = -INFINITY, rmax1 = -INFINITY;
#pragma unroll
        for (int ni = 0; ni < 8; ni++) {
            int c0 = cbase + ni * 8 + 2 * tig;
            float v0 = sacc[ni][0] * ATTN_SCALE;
            float v1 = sacc[ni][1] * ATTN_SCALE;
            float v2 = sacc[ni][2] * ATTN_SCALE;
            float v3 = sacc[ni][3] * ATTN_SCALE;
            if (needmask) {
                if (c0     > row0) v0 = -INFINITY;
                if (c0 + 1 > row0) v1 = -INFINITY;
                if (c0     > row1) v2 = -INFINITY;
                if (c0 + 1 > row1) v3 = -INFINITY;
            }
            sacc[ni][0] = v0; sacc[ni][1] = v1;
            sacc[ni][2] = v2; sacc[ni][3] = v3;
            rmax0 = fmaxf(rmax0, fmaxf(v0, v1));
            rmax1 = fmaxf(rmax1, fmaxf(v2, v3));
        }
        rmax0 = fmaxf(rmax0, __shfl_xor_sync(0xffffffffu, rmax0, 1));
        rmax0 = fmaxf(rmax0, __shfl_xor_sync(0xffffffffu, rmax0, 2));
        rmax1 = fmaxf(rmax1, __shfl_xor_sync(0xffffffffu, rmax1, 1));
        rmax1 = fmaxf(rmax1, __shfl_xor_sync(0xffffffffu, rmax1, 2));

        float mn0 = fmaxf(m0, rmax0);
        float mn1 = fmaxf(m1, rmax1);
        float fr0 = __expf(m0 - mn0);
        float fr1 = __expf(m1 - mn1);
        m0 = mn0; m1 = mn1;

        float sum0 = 0.0f, sum1 = 0.0f;
#pragma unroll
        for (int ni = 0; ni < 8; ni++) {
            float p0 = __expf(sacc[ni][0] - mn0);
            float p1 = __expf(sacc[ni][1] - mn0);
            float p2 = __expf(sacc[ni][2] - mn1);
            float p3 = __expf(sacc[ni][3] - mn1);
            sum0 += p0 + p1;
            sum1 += p2 + p3;
            int cc = ni * 8 + 2 * tig;
            *(float2*)&Ps[(rw + g) * 68 + cc]     = make_float2(tf32r(p0), tf32r(p1));
            *(float2*)&Ps[(rw + g + 8) * 68 + cc] = make_float2(tf32r(p2), tf32r(p3));
        }
        sum0 += __shfl_xor_sync(0xffffffffu, sum0, 1);
        sum0 += __shfl_xor_sync(0xffffffffu, sum0, 2);
        sum1 += __shfl_xor_sync(0xffffffffu, sum1, 1);
        sum1 += __shfl_xor_sync(0xffffffffu, sum1, 2);
        l0 = l0 * fr0 + sum0;
        l1 = l1 * fr1 + sum1;

        // rescale O accumulators
#pragma unroll
        for (int nd = 0; nd < 16; nd++) {
            oacc[nd][0] *= fr0; oacc[nd][1] *= fr0;
            oacc[nd][2] *= fr1; oacc[nd][3] *= fr1;
        }

        // ---- O += P V  (same-warp Ps rows: no barrier needed) ----
#pragma unroll
        for (int s0 = 0; s0 < 64; s0 += 8) {
            float a[4];
            const float* ap = Ps + (rw + g) * 68 + s0 + tig;
            a[0] = ap[0];
            a[1] = ap[8 * 68];
            a[2] = ap[4];
            a[3] = ap[8 * 68 + 4];
#pragma unroll
            for (int nd = 0; nd < 16; nd++) {
                float b[2];
                const float* bp = Vst + (nd * 8 + g) * 68 + s0 + tig;
                b[0] = bp[0];
                b[1] = bp[4];
                mma_tf32(oacc[nd], a, b);
            }
        }
        __syncthreads();   // protect Ks/Vst before next tile load
    }

    // epilogue: normalize and write
    const float inv0 = 1.0f / l0;
    const float inv1 = 1.0f / l1;
    float* dst0 = g_y + (size_t)(qbase + rw + g) * DIM_C + h * HD;
    float* dst1 = dst0 + (size_t)8 * DIM_C;
#pragma unroll
    for (int nd = 0; nd < 16; nd++) {
        int col = nd * 8 + 2 * tig;
        *(float2*)&dst0[col] = make_float2(oacc[nd][0] * inv0, oacc[nd][1] * inv0);
        *(float2*)&dst1[col] = make_float2(oacc[nd][2] * inv1, oacc[nd][3] * inv1);
    }
}

// ---------------------------------------------------------------------------
extern "C" void kernel_launch(void* const* d_in, const int* in_sizes, int n_in,
                              void* d_out, int out_size)
{
    const float* x   = (const float*)d_in[0];   // [1,2048,2048]
    const float* w   = (const float*)d_in[1];   // [4,2048,2048]
    const float* ve  = (const float*)d_in[2];   // [1,2048,2048]
    const float* lam = (const float*)d_in[3];   // [2]
    float* out = (float*)d_out;                 // [1,2048,2048] f32

    float* qkv_ptr = nullptr;
    float* y_ptr   = nullptr;
    cudaGetSymbolAddress((void**)&qkv_ptr, g_qkv);
    cudaGetSymbolAddress((void**)&y_ptr,   g_y);

    const int gemm_smem = 4 * GBUF * (int)sizeof(float);   // 73728 B
    cudaFuncSetAttribute(gemm_tf32_kernel,
                         cudaFuncAttributeMaxDynamicSharedMemorySize, gemm_smem);

    // 1) QKV projection: [2048,2048] x [6144,2048]^T -> g_qkv
    gemm_tf32_kernel<<<dim3(48, 16), 256, gemm_smem>>>(x, w, qkv_ptr, 2048, 6144, 2048);

    // 2) RMSNorm + RoPE + v blend (in-place on g_qkv)
    postproc_kernel<<<dim3(2048, 16), 128>>>(ve, lam);

    // 3) causal attention -> g_y (tensor cores)
    cudaFuncSetAttribute(attn_kernel,
                         cudaFuncAttributeMaxDynamicSharedMemorySize, ATTN_SMEM);
    attn_kernel<<<dim3(16, 16), 256, ATTN_SMEM>>>();

    // 4) output projection: [2048,2048] x [2048,2048]^T -> out
    gemm_tf32_kernel<<<dim3(16, 16), 256, gemm_smem>>>(y_ptr, w + (size_t)3 * 2048 * 2048, out,
                                                       2048, 2048, 2048);
}

// round 4
// speedup vs baseline: 3.4610x; 1.7541x over previous
#include <cuda_runtime.h>
#include <math.h>

#define T_SEQ  2048
#define DIM_C  2048
#define NH     16
#define HD     128
#define QKV_N  6144      // 3 * 2048, row layout [t][e*2048 + h*128 + d]
#define ATTN_SCALE 0.12f

// Scratch
__device__ float g_qkv[(size_t)T_SEQ * QKV_N];   // 50 MB
__device__ float g_y[(size_t)T_SEQ * DIM_C];     // 16 MB

// ---------------------------------------------------------------------------
// tf32 helpers
// ---------------------------------------------------------------------------
__device__ __forceinline__ float tf32r(float x) {
    unsigned u;
    asm("cvt.rna.tf32.f32 %0, %1;" : "=r"(u) : "f"(x));
    return __uint_as_float(u);
}

__device__ __forceinline__ void mma_tf32(float* d, const float* a, const float* b) {
    asm volatile(
        "mma.sync.aligned.m16n8k8.row.col.f32.tf32.tf32.f32 "
        "{%0,%1,%2,%3}, {%4,%5,%6,%7}, {%8,%9}, {%0,%1,%2,%3};\n"
        : "+f"(d[0]), "+f"(d[1]), "+f"(d[2]), "+f"(d[3])
        : "r"(__float_as_uint(a[0])), "r"(__float_as_uint(a[1])),
          "r"(__float_as_uint(a[2])), "r"(__float_as_uint(a[3])),
          "r"(__float_as_uint(b[0])), "r"(__float_as_uint(b[1])));
}

// ---------------------------------------------------------------------------
// GEMM (TN) on tensor cores (unchanged)
// ---------------------------------------------------------------------------
#define GSPAD 36
#define GBUF  (128 * GSPAD)

__global__ __launch_bounds__(256, 2)
void gemm_tf32_kernel(const float* __restrict__ A,
                      const float* __restrict__ B,
                      float* __restrict__ C,
                      int M, int N, int K)
{
    extern __shared__ float smg[];
    float* As = smg;
    float* Bs = smg + 2 * GBUF;

    const int tid  = threadIdx.x;
    const int lane = tid & 31;
    const int wid  = tid >> 5;
    const int g    = lane >> 2;
    const int tig  = lane & 3;

    const int wm = (wid & 1) * 64;
    const int wn = (wid >> 1) * 32;

    const int rowBase = blockIdx.y * 128;
    const int colBase = blockIdx.x * 128;

    const float* Ag = A + (size_t)rowBase * K;
    const float* Bg = B + (size_t)colBase * K;

    const int c4 = (tid & 7) << 2;
    const int r0 = tid >> 3;

    float acc[4][4][4];
#pragma unroll
    for (int mi = 0; mi < 4; mi++)
#pragma unroll
        for (int ni = 0; ni < 4; ni++)
#pragma unroll
            for (int c = 0; c < 4; c++) acc[mi][ni][c] = 0.0f;

#pragma unroll
    for (int i = 0; i < 4; i++) {
        int r = r0 + 32 * i;
        float4 av = *(const float4*)(Ag + (size_t)r * K + c4);
        float4 bv = *(const float4*)(Bg + (size_t)r * K + c4);
        *(float4*)&As[r * GSPAD + c4] =
            make_float4(tf32r(av.x), tf32r(av.y), tf32r(av.z), tf32r(av.w));
        *(float4*)&Bs[r * GSPAD + c4] =
            make_float4(tf32r(bv.x), tf32r(bv.y), tf32r(bv.z), tf32r(bv.w));
    }
    __syncthreads();

    const int nk = K >> 5;
    for (int kt = 0; kt < nk; kt++) {
        const int cur = kt & 1;
        float4 ar[4], br[4];
        const bool pre = (kt + 1 < nk);
        if (pre) {
            int k0 = (kt + 1) << 5;
#pragma unroll
            for (int i = 0; i < 4; i++) {
                int r = r0 + 32 * i;
                ar[i] = *(const float4*)(Ag + (size_t)r * K + k0 + c4);
                br[i] = *(const float4*)(Bg + (size_t)r * K + k0 + c4);
            }
        }

        const float* Ac = As + cur * GBUF;
        const float* Bc = Bs + cur * GBUF;

#pragma unroll
        for (int ks = 0; ks < 4; ks++) {
            const int k0 = ks * 8;
            float a[4][4];
#pragma unroll
            for (int mi = 0; mi < 4; mi++) {
                const float* p  = Ac + (wm + mi * 16 + g) * GSPAD + k0 + tig;
                const float* p8 = p + 8 * GSPAD;
                a[mi][0] = p[0];
                a[mi][1] = p8[0];
                a[mi][2] = p[4];
                a[mi][3] = p8[4];
            }
            float b[4][2];
#pragma unroll
            for (int ni = 0; ni < 4; ni++) {
                const float* p = Bc + (wn + ni * 8 + g) * GSPAD + k0 + tig;
                b[ni][0] = p[0];
                b[ni][1] = p[4];
            }
#pragma unroll
            for (int mi = 0; mi < 4; mi++)
#pragma unroll
                for (int ni = 0; ni < 4; ni++)
                    mma_tf32(acc[mi][ni], a[mi], b[ni]);
        }

        if (pre) {
            float* An = As + (cur ^ 1) * GBUF;
            float* Bn = Bs + (cur ^ 1) * GBUF;
#pragma unroll
            for (int i = 0; i < 4; i++) {
                int r = r0 + 32 * i;
                *(float4*)&An[r * GSPAD + c4] =
                    make_float4(tf32r(ar[i].x), tf32r(ar[i].y), tf32r(ar[i].z), tf32r(ar[i].w));
                *(float4*)&Bn[r * GSPAD + c4] =
                    make_float4(tf32r(br[i].x), tf32r(br[i].y), tf32r(br[i].z), tf32r(br[i].w));
            }
        }
        __syncthreads();
    }

    float* Cp = C + (size_t)rowBase * N + colBase;
#pragma unroll
    for (int mi = 0; mi < 4; mi++) {
        int m = wm + mi * 16 + g;
#pragma unroll
        for (int ni = 0; ni < 4; ni++) {
            int n = wn + ni * 8 + tig * 2;
            *(float2*)&Cp[(size_t)m * N + n] =
                make_float2(acc[mi][ni][0], acc[mi][ni][1]);
            *(float2*)&Cp[(size_t)(m + 8) * N + n] =
                make_float2(acc[mi][ni][2], acc[mi][ni][3]);
        }
    }
}

// ---------------------------------------------------------------------------
// Per (t, h): RMSNorm q/k/v, RoPE q/k, v blend. Writes tf32-RNA-rounded
// values (attention consumes them as tf32 operands directly).
// ---------------------------------------------------------------------------
__global__ void postproc_kernel(const float* __restrict__ ve,
                                const float* __restrict__ lam)
{
    const int t = blockIdx.x;
    const int h = blockIdx.y;
    const int d = threadIdx.x;

    __shared__ float red[4];
    __shared__ float buf[128];

    float* base = g_qkv + (size_t)t * QKV_N + h * HD;
    const float lam0 = lam[0];
    const float lam1 = lam[1];

#pragma unroll
    for (int e = 0; e < 3; e++) {
        float val = base[e * 2048 + d];
        float sq = val * val;
#pragma unroll
        for (int o = 16; o > 0; o >>= 1)
            sq += __shfl_xor_sync(0xffffffffu, sq, o);
        if ((d & 31) == 0) red[d >> 5] = sq;
        __syncthreads();
        float mean = (red[0] + red[1] + red[2] + red[3]) * (1.0f / 128.0f);
        float nv = val * rsqrtf(mean + 1e-6f);

        if (e < 2) {
            buf[d] = nv;
            __syncthreads();
            int j = d & 63;
            float c, sn;
            if (j < 32) {
                float fr = exp2f((-10.0f / 31.0f) * (float)j);
                float th = (float)t * fr;
                c = cosf(th); sn = sinf(th);
            } else {
                c = 1.0f; sn = 0.0f;
            }
            float x1 = buf[j];
            float x2 = buf[j + 64];
            float outv = (d < 64) ? (x1 * c + x2 * sn) : (x2 * c - x1 * sn);
            __syncthreads();
            base[e * 2048 + d] = tf32r(outv);
        } else {
            base[e * 2048 + d] =
                tf32r(lam0 * nv + lam1 * ve[(size_t)t * DIM_C + h * HD + d]);
        }
    }
}

// ---------------------------------------------------------------------------
// Causal flash attention v2 (tf32 mma). Q-tile 64, KV-tile 64.
// 256 threads = 8 warps: wid&3 -> q-row block (16 rows), wid>>2 -> col half
// (32 kv cols for S, 64 d cols for PV). Ps aliases Ks (phase barriers make it
// safe). smem 103.4KB -> 2 CTAs/SM. Inputs pre-rounded to tf32 by postproc.
// ---------------------------------------------------------------------------
#define AQ_OFF   0
#define AKU_OFF  (64 * 132)                 // Ks[64][132] / Ps[64][68] union
#define AV_OFF   (AKU_OFF + 64 * 132)       // Vst[128][68]
#define ARM_OFF  (AV_OFF + 128 * 68)        // rpmax[64][2]
#define ARS_OFF  (ARM_OFF + 128)            // rpsum[64][2]
#define ATTN_SMEM ((ARS_OFF + 128) * 4)     // 103,424 B

__global__ __launch_bounds__(256, 2)
void attn_kernel()
{
    extern __shared__ float sm[];
    float* Qs    = sm + AQ_OFF;
    float* Ks    = sm + AKU_OFF;
    float* Ps    = sm + AKU_OFF;   // alias
    float* Vst   = sm + AV_OFF;
    float* rpmax = sm + ARM_OFF;
    float* rpsum = sm + ARS_OFF;

    const int h     = blockIdx.y;
    const int qt    = 31 - (int)blockIdx.x;   // big tiles first
    const int qbase = qt * 64;
    const int tid   = threadIdx.x;
    const int lane  = tid & 31;
    const int wid   = tid >> 5;
    const int g     = lane >> 2;
    const int tig   = lane & 3;
    const int rw    = (wid & 3) * 16;        // q-row block base
    const int ch    = wid >> 2;              // col half (0/1)

    // Q tile (already tf32): raw copy
    const float* qg = g_qkv + (size_t)qbase * QKV_N + h * HD;
#pragma unroll
    for (int f = tid; f < 64 * 32; f += 256) {
        int r = f >> 5, d4 = (f & 31) << 2;
        *(float4*)&Qs[r * 132 + d4] = *(const float4*)(qg + (size_t)r * QKV_N + d4);
    }

    float oacc[8][4];
#pragma unroll
    for (int nd = 0; nd < 8; nd++)
#pragma unroll
        for (int c = 0; c < 4; c++) oacc[nd][c] = 0.0f;

    float m0 = -INFINITY, m1 = -INFINITY, l0 = 0.0f, l1 = 0.0f;

    const int row0 = qbase + rw + g;
    const int row1 = row0 + 8;

    __syncthreads();

    for (int kb = 0; kb <= qt; kb++) {
        // ---- phase A: load K and V tiles ----
        const float* kg = g_qkv + (size_t)(kb * 64) * QKV_N + 2048 + h * HD;
#pragma unroll
        for (int f = tid; f < 64 * 32; f += 256) {
            int c = f >> 5, d4 = (f & 31) << 2;
            *(float4*)&Ks[c * 132 + d4] = *(const float4*)(kg + (size_t)c * QKV_N + d4);
        }
        const float* vg = g_qkv + (size_t)(kb * 64) * QKV_N + 4096 + h * HD;
#pragma unroll
        for (int f = tid; f < 64 * 32; f += 256) {
            int d4 = (f >> 6) << 2, c = f & 63;
            float4 v = *(const float4*)(vg + (size_t)c * QKV_N + d4);
            Vst[(d4 + 0) * 68 + c] = v.x;
            Vst[(d4 + 1) * 68 + c] = v.y;
            Vst[(d4 + 2) * 68 + c] = v.z;
            Vst[(d4 + 3) * 68 + c] = v.w;
        }
        __syncthreads();   // B1

        // ---- phase B: S = Q K^T (16 rows x 32 cols per warp) ----
        float sacc[4][4];
#pragma unroll
        for (int ni = 0; ni < 4; ni++)
#pragma unroll
            for (int c = 0; c < 4; c++) sacc[ni][c] = 0.0f;

#pragma unroll
        for (int k0 = 0; k0 < 128; k0 += 8) {
            float a[4];
            const float* ap = Qs + (rw + g) * 132 + k0 + tig;
            a[0] = ap[0];
            a[1] = ap[8 * 132];
            a[2] = ap[4];
            a[3] = ap[8 * 132 + 4];
#pragma unroll
            for (int ni = 0; ni < 4; ni++) {
                float b[2];
                const float* bp = Ks + (ch * 32 + ni * 8 + g) * 132 + k0 + tig;
                b[0] = bp[0];
                b[1] = bp[4];
                mma_tf32(sacc[ni], a, b);
            }
        }

        // scale + mask + partial row max
        const int cbase = kb * 64 + ch * 32;
        const bool needmask = (kb == qt);
        float rmax0 = -INFINITY, rmax1 = -INFINITY;
#pragma unroll
        for (int ni = 0; ni < 4; ni++) {
            int c0 = cbase + ni * 8 + 2 * tig;
            float v0 = sacc[ni][0] * ATTN_SCALE;
            float v1 = sacc[ni][1] * ATTN_SCALE;
            float v2 = sacc[ni][2] * ATTN_SCALE;
            float v3 = sacc[ni][3] * ATTN_SCALE;
            if (needmask) {
                if (c0     > row0) v0 = -INFINITY;
                if (c0 + 1 > row0) v1 = -INFINITY;
                if (c0     > row1) v2 = -INFINITY;
                if (c0 + 1 > row1) v3 = -INFINITY;
            }
            sacc[ni][0] = v0; sacc[ni][1] = v1;
            sacc[ni][2] = v2; sacc[ni][3] = v3;
            rmax0 = fmaxf(rmax0, fmaxf(v0, v1));
            rmax1 = fmaxf(rmax1, fmaxf(v2, v3));
        }
        rmax0 = fmaxf(rmax0, __shfl_xor_sync(0xffffffffu, rmax0, 1));
        rmax0 = fmaxf(rmax0, __shfl_xor_sync(0xffffffffu, rmax0, 2));
        rmax1 = fmaxf(rmax1, __shfl_xor_sync(0xffffffffu, rmax1, 1));
        rmax1 = fmaxf(rmax1, __shfl_xor_sync(0xffffffffu, rmax1, 2));
        if (tig == 0) {
            rpmax[(rw + g) * 2 + ch]     = rmax0;
            rpmax[(rw + g + 8) * 2 + ch] = rmax1;
        }
        __syncthreads();   // B2 (Ks consumed; rpmax visible)

        // ---- phase C: softmax, write P (aliases Ks) ----
        float mt0 = fmaxf(rpmax[(rw + g) * 2],     rpmax[(rw + g) * 2 + 1]);
        float mt1 = fmaxf(rpmax[(rw + g + 8) * 2], rpmax[(rw + g + 8) * 2 + 1]);
        float mn0 = fmaxf(m0, mt0);
        float mn1 = fmaxf(m1, mt1);
        float fr0 = __expf(m0 - mn0);
        float fr1 = __expf(m1 - mn1);
        m0 = mn0; m1 = mn1;

        float sum0 = 0.0f, sum1 = 0.0f;
#pragma unroll
        for (int ni = 0; ni < 4; ni++) {
            float p0 = __expf(sacc[ni][0] - mn0);
            float p1 = __expf(sacc[ni][1] - mn0);
            float p2 = __expf(sacc[ni][2] - mn1);
            float p3 = __expf(sacc[ni][3] - mn1);
            sum0 += p0 + p1;
            sum1 += p2 + p3;
            int cc = ch * 32 + ni * 8 + 2 * tig;
            *(float2*)&Ps[(rw + g) * 68 + cc]     = make_float2(tf32r(p0), tf32r(p1));
            *(float2*)&Ps[(rw + g + 8) * 68 + cc] = make_float2(tf32r(p2), tf32r(p3));
        }
        sum0 += __shfl_xor_sync(0xffffffffu, sum0, 1);
        sum0 += __shfl_xor_sync(0xffffffffu, sum0, 2);
        sum1 += __shfl_xor_sync(0xffffffffu, sum1, 1);
        sum1 += __shfl_xor_sync(0xffffffffu, sum1, 2);
        if (tig == 0) {
            rpsum[(rw + g) * 2 + ch]     = sum0;
            rpsum[(rw + g + 8) * 2 + ch] = sum1;
        }
        __syncthreads();   // B3 (P + sums visible)

        // ---- phase D: l update, rescale, O += P V ----
        float st0 = rpsum[(rw + g) * 2]     + rpsum[(rw + g) * 2 + 1];
        float st1 = rpsum[(rw + g + 8) * 2] + rpsum[(rw + g + 8) * 2 + 1];
        l0 = l0 * fr0 + st0;
        l1 = l1 * fr1 + st1;
#pragma unroll
        for (int nd = 0; nd < 8; nd++) {
            oacc[nd][0] *= fr0; oacc[nd][1] *= fr0;
            oacc[nd][2] *= fr1; oacc[nd][3] *= fr1;
        }

#pragma unroll
        for (int s0 = 0; s0 < 64; s0 += 8) {
            float a[4];
            const float* ap = Ps + (rw + g) * 68 + s0 + tig;
            a[0] = ap[0];
            a[1] = ap[8 * 68];
            a[2] = ap[4];
            a[3] = ap[8 * 68 + 4];
#pragma unroll
            for (int nd = 0; nd < 8; nd++) {
                float b[2];
                const float* bp = Vst + (ch * 64 + nd * 8 + g) * 68 + s0 + tig;
                b[0] = bp[0];
                b[1] = bp[4];
                mma_tf32(oacc[nd], a, b);
            }
        }
        __syncthreads();   // B4 (Ps/Vst consumed before next load)
    }

    // epilogue
    const float inv0 = 1.0f / l0;
    const float inv1 = 1.0f / l1;
    float* dst0 = g_y + (size_t)row0 * DIM_C + h * HD + ch * 64;
    float* dst1 = g_y + (size_t)row1 * DIM_C + h * HD + ch * 64;
#pragma unroll
    for (int nd = 0; nd < 8; nd++) {
        int col = nd * 8 + 2 * tig;
        *(float2*)&dst0[col] = make_float2(oacc[nd][0] * inv0, oacc[nd][1] * inv0);
        *(float2*)&dst1[col] = make_float2(oacc[nd][2] * inv1, oacc[nd][3] * inv1);
    }
}

// ---------------------------------------------------------------------------
extern "C" void kernel_launch(void* const* d_in, const int* in_sizes, int n_in,
                              void* d_out, int out_size)
{
    const float* x   = (const float*)d_in[0];   // [1,2048,2048]
    const float* w   = (const float*)d_in[1];   // [4,2048,2048]
    const float* ve  = (const float*)d_in[2];   // [1,2048,2048]
    const float* lam = (const float*)d_in[3];   // [2]
    float* out = (float*)d_out;                 // [1,2048,2048] f32

    float* qkv_ptr = nullptr;
    float* y_ptr   = nullptr;
    cudaGetSymbolAddress((void**)&qkv_ptr, g_qkv);
    cudaGetSymbolAddress((void**)&y_ptr,   g_y);

    const int gemm_smem = 4 * GBUF * (int)sizeof(float);   // 73728 B
    cudaFuncSetAttribute(gemm_tf32_kernel,
                         cudaFuncAttributeMaxDynamicSharedMemorySize, gemm_smem);

    // 1) QKV projection
    gemm_tf32_kernel<<<dim3(48, 16), 256, gemm_smem>>>(x, w, qkv_ptr, 2048, 6144, 2048);

    // 2) RMSNorm + RoPE + v blend (writes tf32-rounded q/k/v)
    postproc_kernel<<<dim3(2048, 16), 128>>>(ve, lam);

    // 3) causal attention
    cudaFuncSetAttribute(attn_kernel,
                         cudaFuncAttributeMaxDynamicSharedMemorySize, ATTN_SMEM);
    attn_kernel<<<dim3(32, 16), 256, ATTN_SMEM>>>();

    // 4) output projection
    gemm_tf32_kernel<<<dim3(16, 16), 256, gemm_smem>>>(y_ptr, w + (size_t)3 * 2048 * 2048, out,
                                                       2048, 2048, 2048);
}